// round 2
// baseline (speedup 1.0000x reference)
#include <cuda_runtime.h>

#define N_  32768
#define NZ_ 512
#define H_  1024
#define C_  128
#define K_  8

#define BN 64
#define BH 64
#define BZ 64
#define TPB 256

// scratch for soft-assignment weights (static device global: allowed)
__device__ float g_q[N_ * K_];

// ---------------------------------------------------------------------------
// Kernel 1: student-t soft assignment q[n,k]
// one warp per row n; centers staged in smem
// ---------------------------------------------------------------------------
__global__ void q_kernel(const float* __restrict__ z,
                         const float* __restrict__ mu) {
    __shared__ float smu[K_ * NZ_];
    for (int i = threadIdx.x; i < K_ * NZ_; i += blockDim.x) smu[i] = mu[i];
    __syncthreads();

    int gwarp = (blockIdx.x * blockDim.x + threadIdx.x) >> 5;  // row n
    int lane  = threadIdx.x & 31;
    if (gwarp >= N_) return;

    const float* zr = z + (size_t)gwarp * NZ_;
    float acc[K_];
#pragma unroll
    for (int k = 0; k < K_; k++) acc[k] = 0.f;

    for (int j = lane; j < NZ_; j += 32) {
        float zj = zr[j];
#pragma unroll
        for (int k = 0; k < K_; k++) {
            float d = zj - smu[k * NZ_ + j];
            acc[k] = fmaf(d, d, acc[k]);
        }
    }
#pragma unroll
    for (int k = 0; k < K_; k++) {
#pragma unroll
        for (int o = 16; o > 0; o >>= 1)
            acc[k] += __shfl_xor_sync(0xffffffffu, acc[k], o);
    }
    if (lane == 0) {
        float w[K_];
        float s = 0.f;
#pragma unroll
        for (int k = 0; k < K_; k++) { w[k] = 1.f / (1.f + acc[k]); s += w[k]; }
        float inv = 1.f / s;
#pragma unroll
        for (int k = 0; k < K_; k++) g_q[gwarp * K_ + k] = w[k] * inv;
    }
}

// ---------------------------------------------------------------------------
// Kernel 2: fused  relu(z@W1+b1)@W2+b2, q-weighted sum over K experts.
// Block: 64 rows x 128 cols of output, 256 threads (16x16),
// thread micro-tile 4x8. Loops all K experts internally (no atomics).
// smem: poolA (32KB) holds {zs|ws} during layer-1, aliased by w2s in layer-2.
// ---------------------------------------------------------------------------
__global__ void __launch_bounds__(TPB, 2) fused_kernel(
    const float* __restrict__ z,  const float* __restrict__ W1,
    const float* __restrict__ b1, const float* __restrict__ W2,
    const float* __restrict__ b2, float* __restrict__ out)
{
    __shared__ float poolA[2 * BN * BZ];   // 8192 floats = 32KB
    __shared__ float hbuf[BN * BH];        // 4096 floats = 16KB

    float* zs  = poolA;             // [BN][BZ]
    float* ws  = poolA + BN * BZ;   // [BZ][BH]
    float* w2s = poolA;             // [BH][C_]  (aliases zs+ws; 8192 floats)

    const int tid = threadIdx.x;
    const int tx  = tid & 15;   // 0..15 -> output cols tx*8..+7
    const int ty  = tid >> 4;   // 0..15 -> output rows ty*4..+3
    const int n0  = blockIdx.x * BN;

    float outacc[4][8];
#pragma unroll
    for (int r = 0; r < 4; r++)
#pragma unroll
        for (int c = 0; c < 8; c++) outacc[r][c] = 0.f;

    for (int k = 0; k < K_; k++) {
        float acc[4][8];
#pragma unroll
        for (int r = 0; r < 4; r++)
#pragma unroll
            for (int c = 0; c < 8; c++) acc[r][c] = 0.f;

        for (int ht = 0; ht < H_; ht += BH) {
            // ---------------- layer 1: hbuf = relu(z_tile @ W1 + b1) -------
            float hacc[4][4];
#pragma unroll
            for (int r = 0; r < 4; r++)
#pragma unroll
                for (int c = 0; c < 4; c++) hacc[r][c] = 0.f;

            for (int zb = 0; zb < NZ_; zb += BZ) {
                // zs[row][col] = z[n0+row][zb+col]   (1024 float4, 4/thread)
#pragma unroll
                for (int v = 0; v < 4; v++) {
                    int lin = tid + v * TPB;
                    int row = lin >> 4;
                    int c4  = (lin & 15) << 2;
                    *(float4*)&zs[row * BZ + c4] =
                        *(const float4*)&z[(size_t)(n0 + row) * NZ_ + zb + c4];
                }
                // ws[row][col] = W1[k][zb+row][ht+col]
#pragma unroll
                for (int v = 0; v < 4; v++) {
                    int lin = tid + v * TPB;
                    int row = lin >> 4;
                    int c4  = (lin & 15) << 2;
                    *(float4*)&ws[row * BH + c4] =
                        *(const float4*)&W1[((size_t)k * NZ_ + zb + row) * H_ + ht + c4];
                }
                __syncthreads();

#pragma unroll 8
                for (int p = 0; p < BZ; p++) {
                    float4 wv = *(float4*)&ws[p * BH + tx * 4];
                    float za0 = zs[(ty * 4 + 0) * BZ + p];
                    float za1 = zs[(ty * 4 + 1) * BZ + p];
                    float za2 = zs[(ty * 4 + 2) * BZ + p];
                    float za3 = zs[(ty * 4 + 3) * BZ + p];
                    hacc[0][0] = fmaf(za0, wv.x, hacc[0][0]);
                    hacc[0][1] = fmaf(za0, wv.y, hacc[0][1]);
                    hacc[0][2] = fmaf(za0, wv.z, hacc[0][2]);
                    hacc[0][3] = fmaf(za0, wv.w, hacc[0][3]);
                    hacc[1][0] = fmaf(za1, wv.x, hacc[1][0]);
                    hacc[1][1] = fmaf(za1, wv.y, hacc[1][1]);
                    hacc[1][2] = fmaf(za1, wv.z, hacc[1][2]);
                    hacc[1][3] = fmaf(za1, wv.w, hacc[1][3]);
                    hacc[2][0] = fmaf(za2, wv.x, hacc[2][0]);
                    hacc[2][1] = fmaf(za2, wv.y, hacc[2][1]);
                    hacc[2][2] = fmaf(za2, wv.z, hacc[2][2]);
                    hacc[2][3] = fmaf(za2, wv.w, hacc[2][3]);
                    hacc[3][0] = fmaf(za3, wv.x, hacc[3][0]);
                    hacc[3][1] = fmaf(za3, wv.y, hacc[3][1]);
                    hacc[3][2] = fmaf(za3, wv.z, hacc[3][2]);
                    hacc[3][3] = fmaf(za3, wv.w, hacc[3][3]);
                }
                __syncthreads();
            }

            // bias + relu -> hbuf[row][hcol]
#pragma unroll
            for (int r = 0; r < 4; r++) {
#pragma unroll
                for (int c = 0; c < 4; c++) {
                    float v = hacc[r][c] + b1[(size_t)k * H_ + ht + tx * 4 + c];
                    hbuf[(ty * 4 + r) * BH + tx * 4 + c] = fmaxf(v, 0.f);
                }
            }
            __syncthreads();   // hbuf visible; poolA (zs/ws) free to reuse

            // ---------------- layer 2: acc += hbuf @ W2 tile ---------------
            // w2s[row][col] = W2[k][ht+row][col]   (2048 float4, 8/thread)
#pragma unroll
            for (int v = 0; v < 8; v++) {
                int lin = tid + v * TPB;
                int row = lin >> 5;          // / 32
                int c4  = (lin & 31) << 2;
                *(float4*)&w2s[row * C_ + c4] =
                    *(const float4*)&W2[((size_t)k * H_ + ht + row) * C_ + c4];
            }
            __syncthreads();

#pragma unroll 8
            for (int p = 0; p < BH; p++) {
                float4 wa = *(float4*)&w2s[p * C_ + tx * 8];
                float4 wb = *(float4*)&w2s[p * C_ + tx * 8 + 4];
                float hv0 = hbuf[(ty * 4 + 0) * BH + p];
                float hv1 = hbuf[(ty * 4 + 1) * BH + p];
                float hv2 = hbuf[(ty * 4 + 2) * BH + p];
                float hv3 = hbuf[(ty * 4 + 3) * BH + p];
                acc[0][0] = fmaf(hv0, wa.x, acc[0][0]);
                acc[0][1] = fmaf(hv0, wa.y, acc[0][1]);
                acc[0][2] = fmaf(hv0, wa.z, acc[0][2]);
                acc[0][3] = fmaf(hv0, wa.w, acc[0][3]);
                acc[0][4] = fmaf(hv0, wb.x, acc[0][4]);
                acc[0][5] = fmaf(hv0, wb.y, acc[0][5]);
                acc[0][6] = fmaf(hv0, wb.z, acc[0][6]);
                acc[0][7] = fmaf(hv0, wb.w, acc[0][7]);
                acc[1][0] = fmaf(hv1, wa.x, acc[1][0]);
                acc[1][1] = fmaf(hv1, wa.y, acc[1][1]);
                acc[1][2] = fmaf(hv1, wa.z, acc[1][2]);
                acc[1][3] = fmaf(hv1, wa.w, acc[1][3]);
                acc[1][4] = fmaf(hv1, wb.x, acc[1][4]);
                acc[1][5] = fmaf(hv1, wb.y, acc[1][5]);
                acc[1][6] = fmaf(hv1, wb.z, acc[1][6]);
                acc[1][7] = fmaf(hv1, wb.w, acc[1][7]);
                acc[2][0] = fmaf(hv2, wa.x, acc[2][0]);
                acc[2][1] = fmaf(hv2, wa.y, acc[2][1]);
                acc[2][2] = fmaf(hv2, wa.z, acc[2][2]);
                acc[2][3] = fmaf(hv2, wa.w, acc[2][3]);
                acc[2][4] = fmaf(hv2, wb.x, acc[2][4]);
                acc[2][5] = fmaf(hv2, wb.y, acc[2][5]);
                acc[2][6] = fmaf(hv2, wb.z, acc[2][6]);
                acc[2][7] = fmaf(hv2, wb.w, acc[2][7]);
                acc[3][0] = fmaf(hv3, wa.x, acc[3][0]);
                acc[3][1] = fmaf(hv3, wa.y, acc[3][1]);
                acc[3][2] = fmaf(hv3, wa.z, acc[3][2]);
                acc[3][3] = fmaf(hv3, wa.w, acc[3][3]);
                acc[3][4] = fmaf(hv3, wb.x, acc[3][4]);
                acc[3][5] = fmaf(hv3, wb.y, acc[3][5]);
                acc[3][6] = fmaf(hv3, wb.z, acc[3][6]);
                acc[3][7] = fmaf(hv3, wb.w, acc[3][7]);
            }
            __syncthreads();   // before next ht iter reuses poolA / hbuf
        }

        // ------------- combine: outacc += q[n,k] * (acc + b2[k]) ----------
#pragma unroll
        for (int r = 0; r < 4; r++) {
            float qv = g_q[(size_t)(n0 + ty * 4 + r) * K_ + k];
#pragma unroll
            for (int c = 0; c < 8; c++) {
                int cc = tx * 8 + c;
                outacc[r][c] = fmaf(qv, acc[r][c] + b2[k * C_ + cc], outacc[r][c]);
            }
        }
    }

    // write preds
#pragma unroll
    for (int r = 0; r < 4; r++) {
        float4 o0 = make_float4(outacc[r][0], outacc[r][1], outacc[r][2], outacc[r][3]);
        float4 o1 = make_float4(outacc[r][4], outacc[r][5], outacc[r][6], outacc[r][7]);
        float* orow = out + (size_t)(n0 + ty * 4 + r) * C_ + tx * 8;
        *(float4*)(orow)     = o0;
        *(float4*)(orow + 4) = o1;
    }
}

// ---------------------------------------------------------------------------
extern "C" void kernel_launch(void* const* d_in, const int* in_sizes, int n_in,
                              void* d_out, int out_size) {
    const float* z  = (const float*)d_in[0];  // [N, NZ]
    const float* mu = (const float*)d_in[1];  // [K, NZ]
    const float* W1 = (const float*)d_in[2];  // [K, NZ, H]
    const float* b1 = (const float*)d_in[3];  // [K, H]
    const float* W2 = (const float*)d_in[4];  // [K, H, C]
    const float* b2 = (const float*)d_in[5];  // [K, C]
    float* out = (float*)d_out;               // [N, C]

    q_kernel<<<(N_ * 32) / TPB, TPB>>>(z, mu);
    fused_kernel<<<N_ / BN, TPB>>>(z, W1, b1, W2, b2, out);
}

// round 6
// speedup vs baseline: 3.4596x; 3.4596x over previous
#include <cuda_runtime.h>
#include <cstdint>

#define N_  32768
#define NZ_ 512
#define H_  1024
#define C_  128
#define K_  8
#define TPB 256
#define BM  128          // rows per CTA
#define BH  128          // h columns per chunk
#define LDT 36           // staging tile pitch (floats): 32 + 4 pad
#define LDH 132          // h buffer pitch (floats): 128 + 4 pad

// ---------------- device scratch (static globals: allowed) -----------------
__device__ float g_q[N_ * K_];
__device__ float g_zt[N_ * NZ_];         // tf32-rounded z
__device__ float g_w1t[K_ * H_ * NZ_];   // [K][H][NZ]  (tf32-rounded, n-major)
__device__ float g_w2t[K_ * C_ * H_];    // [K][C][H]   (tf32-rounded, n-major)

// ---------------- helpers ---------------------------------------------------
__device__ __forceinline__ uint32_t smem_u32(const void* p) {
    uint32_t a;
    asm("{ .reg .u64 t; cvta.to.shared.u64 t, %1; cvt.u32.u64 %0, t; }" : "=r"(a) : "l"(p));
    return a;
}
__device__ __forceinline__ float tf32r(float x) {
    uint32_t u; asm("cvt.rna.tf32.f32 %0, %1;" : "=r"(u) : "f"(x));
    return __uint_as_float(u);
}
__device__ __forceinline__ void cp16(uint32_t s, const void* g) {
    asm volatile("cp.async.cg.shared.global [%0], [%1], 16;" :: "r"(s), "l"(g) : "memory");
}
#define CP_COMMIT() asm volatile("cp.async.commit_group;" ::: "memory")
#define CP_WAIT0()  asm volatile("cp.async.wait_group 0;" ::: "memory")

// m16n8k8 tf32 mma: A row-major (4 regs), B col-major i.e. [n][k] (2 regs)
__device__ __forceinline__ void mma8(float* c, const uint32_t* a, uint32_t b0, uint32_t b1) {
    asm volatile(
        "mma.sync.aligned.m16n8k8.row.col.f32.tf32.tf32.f32 "
        "{%0,%1,%2,%3}, {%4,%5,%6,%7}, {%8,%9}, {%0,%1,%2,%3};"
        : "+f"(c[0]), "+f"(c[1]), "+f"(c[2]), "+f"(c[3])
        : "r"(a[0]), "r"(a[1]), "r"(a[2]), "r"(a[3]), "r"(b0), "r"(b1));
}

// ---------------------------------------------------------------------------
// prep kernels
// ---------------------------------------------------------------------------
__global__ void zround_kernel(const float* __restrict__ z) {
    int i = blockIdx.x * blockDim.x + threadIdx.x;
    float4 v = ((const float4*)z)[i];
    v.x = tf32r(v.x); v.y = tf32r(v.y); v.z = tf32r(v.z); v.w = tf32r(v.w);
    ((float4*)g_zt)[i] = v;
}

__global__ void transpose_kernel(const float* __restrict__ src, float* __restrict__ dst,
                                 int R, int Cc) {
    __shared__ float t[32][33];
    int b  = blockIdx.z;
    int r0 = blockIdx.y * 32, c0 = blockIdx.x * 32;
    const float* s = src + (size_t)b * R * Cc;
    float* d = dst + (size_t)b * R * Cc;
    int tx = threadIdx.x, ty = threadIdx.y;
#pragma unroll
    for (int i = 0; i < 32; i += 8)
        t[ty + i][tx] = tf32r(s[(size_t)(r0 + ty + i) * Cc + c0 + tx]);
    __syncthreads();
#pragma unroll
    for (int i = 0; i < 32; i += 8)
        d[(size_t)(c0 + ty + i) * R + r0 + tx] = t[tx][ty + i];
}

__global__ void q_kernel(const float* __restrict__ z, const float* __restrict__ mu) {
    __shared__ float smu[K_ * NZ_];
    for (int i = threadIdx.x; i < K_ * NZ_; i += blockDim.x) smu[i] = mu[i];
    __syncthreads();
    int gwarp = (blockIdx.x * blockDim.x + threadIdx.x) >> 5;
    int lane  = threadIdx.x & 31;
    if (gwarp >= N_) return;
    const float* zr = z + (size_t)gwarp * NZ_;
    float acc[K_];
#pragma unroll
    for (int k = 0; k < K_; k++) acc[k] = 0.f;
    for (int j = lane; j < NZ_; j += 32) {
        float zj = zr[j];
#pragma unroll
        for (int k = 0; k < K_; k++) {
            float d = zj - smu[k * NZ_ + j];
            acc[k] = fmaf(d, d, acc[k]);
        }
    }
#pragma unroll
    for (int k = 0; k < K_; k++)
#pragma unroll
        for (int o = 16; o > 0; o >>= 1)
            acc[k] += __shfl_xor_sync(0xffffffffu, acc[k], o);
    if (lane == 0) {
        float w[K_], s = 0.f;
#pragma unroll
        for (int k = 0; k < K_; k++) { w[k] = 1.f / (1.f + acc[k]); s += w[k]; }
        float inv = 1.f / s;
#pragma unroll
        for (int k = 0; k < K_; k++) g_q[gwarp * K_ + k] = w[k] * inv;
    }
}

// ---------------------------------------------------------------------------
// fused mma.sync tf32 pipeline, q folded into ReLU.
//   per (expert, h-chunk of 128):
//     GEMM1: hacc[128,128] = zt @ W1T^T      (16 pipelined K=32 subtiles)
//     hs = tf32(q * relu(hacc + b1))
//     GEMM2: outacc[128,128] += hs @ W2T^T   (4 pipelined K=32 subtiles)
//   final: out = outacc + q @ b2
// ---------------------------------------------------------------------------
#define OFF_BUFA0 0
#define OFF_BUFA1 18432
#define OFF_BUFB0 36864
#define OFF_BUFB1 55296
#define OFF_HS    73728
#define OFF_B2S   141312
#define OFF_B1S   145408
#define SMEM_DYN  (146 * 1024)

__global__ void __launch_bounds__(TPB, 1) fused_mma(
    const float* __restrict__ b1, const float* __restrict__ b2,
    float* __restrict__ out)
{
    extern __shared__ char sm[];
    float* const hs  = (float*)(sm + OFF_HS);
    float* const b2s = (float*)(sm + OFF_B2S);
    float* const b1s = (float*)(sm + OFF_B1S);

    const uint32_t sb = smem_u32(sm);
    const uint32_t uA[2] = { sb + OFF_BUFA0, sb + OFF_BUFA1 };
    const uint32_t uB[2] = { sb + OFF_BUFB0, sb + OFF_BUFB1 };
    const uint32_t* const pA[2] = { (const uint32_t*)(sm + OFF_BUFA0),
                                    (const uint32_t*)(sm + OFF_BUFA1) };
    const uint32_t* const pB[2] = { (const uint32_t*)(sm + OFF_BUFB0),
                                    (const uint32_t*)(sm + OFF_BUFB1) };

    const int tid  = threadIdx.x;
    const int lane = tid & 31;
    const int warp = tid >> 5;
    const int wm   = warp & 3;       // 0..3 -> row block of 32
    const int wn   = warp >> 2;      // 0..1 -> col block of 64
    const int gr   = lane >> 2;      // group id 0..7
    const int tig  = lane & 3;       // thread in group
    const int rbase = wm * 32;
    const int cbase = wn * 64;
    const int n0   = blockIdx.x * BM;

    // per-thread staging coordinates (4 cp16 per buffer fill)
    const int srow0 = tid >> 1;             // 0..127 (2 threads per row)
    const int sseg0 = (tid & 1) * 4;        // segment 0 or 4 (x4 over v)

    for (int i = tid; i < K_ * C_; i += TPB) b2s[i] = b2[i];

    float outacc[64];
#pragma unroll
    for (int i = 0; i < 64; i++) outacc[i] = 0.f;

    for (int k = 0; k < K_; k++) {
        const float* w1base = g_w1t + (size_t)k * H_ * NZ_;
        const float* w2base = g_w2t + (size_t)k * C_ * H_;

        for (int ht = 0; ht < H_; ht += BH) {
            __syncthreads();   // prev chunk fully consumed (hs, b1s, buffers)
            if (tid < BH) b1s[tid] = b1[k * H_ + ht + tid];

            float hacc[64];
#pragma unroll
            for (int i = 0; i < 64; i++) hacc[i] = 0.f;

            // ================= GEMM1: 16 K-subtiles of 32 ==================
            // prologue: stage subtile 0 into buf 0
            {
#pragma unroll
                for (int v = 0; v < 4; v++) {
                    int row = tid >> 3, seg = ((tid & 7) );
                    (void)row; (void)seg;
                }
                // A: z tile [128 x 32]  (1024 16B segs; 4 per thread)
#pragma unroll
                for (int v = 0; v < 4; v++) {
                    int lin = tid + v * TPB;
                    int row = lin >> 3, seg = lin & 7;
                    cp16(uA[0] + row * (LDT * 4) + seg * 16,
                         g_zt + (size_t)(n0 + row) * NZ_ + seg * 4);
                }
                // B: W1T tile [128 x 32]
#pragma unroll
                for (int v = 0; v < 4; v++) {
                    int lin = tid + v * TPB;
                    int row = lin >> 3, seg = lin & 7;
                    cp16(uB[0] + row * (LDT * 4) + seg * 16,
                         w1base + (size_t)(ht + row) * NZ_ + seg * 4);
                }
                CP_COMMIT();
            }
            for (int s = 0; s < 16; s++) {
                const int buf = s & 1;
                CP_WAIT0();          // subtile s landed (had compute(s-1) to hide)
                __syncthreads();     // all warps past compute(s-1); buf^1 free
                if (s < 15) {        // prefetch subtile s+1 into buf^1
                    const int nb = buf ^ 1;
                    const int zb = (s + 1) * 32;
#pragma unroll
                    for (int v = 0; v < 4; v++) {
                        int lin = tid + v * TPB;
                        int row = lin >> 3, seg = lin & 7;
                        cp16(uA[nb] + row * (LDT * 4) + seg * 16,
                             g_zt + (size_t)(n0 + row) * NZ_ + zb + seg * 4);
                    }
#pragma unroll
                    for (int v = 0; v < 4; v++) {
                        int lin = tid + v * TPB;
                        int row = lin >> 3, seg = lin & 7;
                        cp16(uB[nb] + row * (LDT * 4) + seg * 16,
                             w1base + (size_t)(ht + row) * NZ_ + zb + seg * 4);
                    }
                    CP_COMMIT();
                }
                // compute on buf
#pragma unroll
                for (int k8 = 0; k8 < 4; k8++) {
                    uint32_t a[2][4];
#pragma unroll
                    for (int tm = 0; tm < 2; tm++) {
                        int r = rbase + tm * 16 + gr;
                        a[tm][0] = pA[buf][r * LDT + k8 * 8 + tig];
                        a[tm][1] = pA[buf][(r + 8) * LDT + k8 * 8 + tig];
                        a[tm][2] = pA[buf][r * LDT + k8 * 8 + tig + 4];
                        a[tm][3] = pA[buf][(r + 8) * LDT + k8 * 8 + tig + 4];
                    }
#pragma unroll
                    for (int tn = 0; tn < 8; tn++) {
                        int nrow = cbase + tn * 8 + gr;
                        uint32_t b0 = pB[buf][nrow * LDT + k8 * 8 + tig];
                        uint32_t b1r = pB[buf][nrow * LDT + k8 * 8 + tig + 4];
#pragma unroll
                        for (int tm = 0; tm < 2; tm++)
                            mma8(&hacc[(tm * 8 + tn) * 4], a[tm], b0, b1r);
                    }
                }
            }

            // ---- hs = tf32(q * relu(hacc + b1)) ----
#pragma unroll
            for (int tm = 0; tm < 2; tm++) {
                int r0 = rbase + tm * 16 + gr;
                float qa = g_q[(size_t)(n0 + r0) * K_ + k];
                float qb = g_q[(size_t)(n0 + r0 + 8) * K_ + k];
#pragma unroll
                for (int tn = 0; tn < 8; tn++) {
                    int idx = (tm * 8 + tn) * 4;
                    int c0  = cbase + tn * 8 + 2 * tig;
                    float2 v0, v1;
                    v0.x = tf32r(fmaxf(hacc[idx + 0] + b1s[c0], 0.f) * qa);
                    v0.y = tf32r(fmaxf(hacc[idx + 1] + b1s[c0 + 1], 0.f) * qa);
                    v1.x = tf32r(fmaxf(hacc[idx + 2] + b1s[c0], 0.f) * qb);
                    v1.y = tf32r(fmaxf(hacc[idx + 3] + b1s[c0 + 1], 0.f) * qb);
                    *(float2*)&hs[r0 * LDH + c0] = v0;
                    *(float2*)&hs[(r0 + 8) * LDH + c0] = v1;
                }
            }
            __syncthreads();   // hs visible to all warps

            // ================= GEMM2: 4 K-subtiles of 32 ===================
            {
                // prologue: stage W2T subtile 0 into bufB 0
#pragma unroll
                for (int v = 0; v < 4; v++) {
                    int lin = tid + v * TPB;
                    int row = lin >> 3, seg = lin & 7;   // row = C index
                    cp16(uB[0] + row * (LDT * 4) + seg * 16,
                         w2base + (size_t)row * H_ + ht + seg * 4);
                }
                CP_COMMIT();
            }
            for (int s = 0; s < 4; s++) {
                const int buf = s & 1;
                CP_WAIT0();
                __syncthreads();
                if (s < 3) {
                    const int nb = buf ^ 1;
                    const int hb = (s + 1) * 32;
#pragma unroll
                    for (int v = 0; v < 4; v++) {
                        int lin = tid + v * TPB;
                        int row = lin >> 3, seg = lin & 7;
                        cp16(uB[nb] + row * (LDT * 4) + seg * 16,
                             w2base + (size_t)row * H_ + ht + hb + seg * 4);
                    }
                    CP_COMMIT();
                }
                const int hb = s * 32;
#pragma unroll
                for (int k8 = 0; k8 < 4; k8++) {
                    uint32_t a[2][4];
#pragma unroll
                    for (int tm = 0; tm < 2; tm++) {
                        int r = rbase + tm * 16 + gr;
                        const uint32_t* hrow  = (const uint32_t*)&hs[r * LDH];
                        const uint32_t* hrow8 = (const uint32_t*)&hs[(r + 8) * LDH];
                        a[tm][0] = hrow[hb + k8 * 8 + tig];
                        a[tm][1] = hrow8[hb + k8 * 8 + tig];
                        a[tm][2] = hrow[hb + k8 * 8 + tig + 4];
                        a[tm][3] = hrow8[hb + k8 * 8 + tig + 4];
                    }
#pragma unroll
                    for (int tn = 0; tn < 8; tn++) {
                        int nrow = cbase + tn * 8 + gr;
                        uint32_t b0 = pB[buf][nrow * LDT + k8 * 8 + tig];
                        uint32_t b1r = pB[buf][nrow * LDT + k8 * 8 + tig + 4];
#pragma unroll
                        for (int tm = 0; tm < 2; tm++)
                            mma8(&outacc[(tm * 8 + tn) * 4], a[tm], b0, b1r);
                    }
                }
            }
        } // ht
    } // experts

    // ---- epilogue: out = outacc + q @ b2 ----
#pragma unroll
    for (int tm = 0; tm < 2; tm++) {
        int r0 = rbase + tm * 16 + gr;
        float qa[K_], qb[K_];
#pragma unroll
        for (int k = 0; k < K_; k++) {
            qa[k] = g_q[(size_t)(n0 + r0) * K_ + k];
            qb[k] = g_q[(size_t)(n0 + r0 + 8) * K_ + k];
        }
#pragma unroll
        for (int tn = 0; tn < 8; tn++) {
            int idx = (tm * 8 + tn) * 4;
            int c0  = cbase + tn * 8 + 2 * tig;
            float v00 = outacc[idx + 0], v01 = outacc[idx + 1];
            float v10 = outacc[idx + 2], v11 = outacc[idx + 3];
#pragma unroll
            for (int k = 0; k < K_; k++) {
                v00 = fmaf(qa[k], b2s[k * C_ + c0],     v00);
                v01 = fmaf(qa[k], b2s[k * C_ + c0 + 1], v01);
                v10 = fmaf(qb[k], b2s[k * C_ + c0],     v10);
                v11 = fmaf(qb[k], b2s[k * C_ + c0 + 1], v11);
            }
            *(float2*)&out[(size_t)(n0 + r0) * C_ + c0]     = make_float2(v00, v01);
            *(float2*)&out[(size_t)(n0 + r0 + 8) * C_ + c0] = make_float2(v10, v11);
        }
    }
}

// ---------------------------------------------------------------------------
extern "C" void kernel_launch(void* const* d_in, const int* in_sizes, int n_in,
                              void* d_out, int out_size) {
    const float* z  = (const float*)d_in[0];  // [N, NZ]
    const float* mu = (const float*)d_in[1];  // [K, NZ]
    const float* W1 = (const float*)d_in[2];  // [K, NZ, H]
    const float* b1 = (const float*)d_in[3];  // [K, H]
    const float* W2 = (const float*)d_in[4];  // [K, H, C]
    const float* b2 = (const float*)d_in[5];  // [K, C]
    float* out = (float*)d_out;               // [N, C]

    cudaFuncSetAttribute(fused_mma, cudaFuncAttributeMaxDynamicSharedMemorySize, SMEM_DYN);

    zround_kernel<<<(N_ * NZ_ / 4) / TPB, TPB>>>(z);
    float* w1t; cudaGetSymbolAddress((void**)&w1t, g_w1t);
    float* w2t; cudaGetSymbolAddress((void**)&w2t, g_w2t);
    transpose_kernel<<<dim3(H_ / 32, NZ_ / 32, K_), dim3(32, 8)>>>(W1, w1t, NZ_, H_);
    transpose_kernel<<<dim3(C_ / 32, H_ / 32, K_), dim3(32, 8)>>>(W2, w2t, H_, C_);
    q_kernel<<<(N_ * 32) / TPB, TPB>>>(z, mu);
    fused_mma<<<N_ / BM, TPB, SMEM_DYN>>>(b1, b2, out);
}

// round 7
// speedup vs baseline: 3.8399x; 1.1099x over previous
#include <cuda_runtime.h>
#include <cstdint>

#define N_  32768
#define NZ_ 512
#define H_  1024
#define C_  128
#define K_  8
#define TPB 256
#define BM  128          // rows per CTA
#define BH  128          // h columns per chunk
#define LDT 36           // staging tile pitch (floats): 32 + 4 pad
#define LDH 132          // h buffer pitch (floats): 128 + 4 pad

// ---------------- device scratch (static globals: allowed) -----------------
__device__ float g_q[N_ * K_];
__device__ float g_zt[N_ * NZ_];         // tf32-rounded z
__device__ float g_w1t[K_ * H_ * NZ_];   // [K][H][NZ]  (tf32-rounded, n-major)
__device__ float g_w2t[K_ * C_ * H_];    // [K][C][H]   (tf32-rounded, n-major)

// ---------------- helpers ---------------------------------------------------
__device__ __forceinline__ uint32_t smem_u32(const void* p) {
    uint32_t a;
    asm("{ .reg .u64 t; cvta.to.shared.u64 t, %1; cvt.u32.u64 %0, t; }" : "=r"(a) : "l"(p));
    return a;
}
__device__ __forceinline__ float tf32r(float x) {
    uint32_t u; asm("cvt.rna.tf32.f32 %0, %1;" : "=r"(u) : "f"(x));
    return __uint_as_float(u);
}
__device__ __forceinline__ void cp16(uint32_t s, const void* g) {
    asm volatile("cp.async.cg.shared.global [%0], [%1], 16;" :: "r"(s), "l"(g) : "memory");
}
#define CP_COMMIT() asm volatile("cp.async.commit_group;" ::: "memory")
#define CP_WAIT0()  asm volatile("cp.async.wait_group 0;" ::: "memory")

// ldmatrix x4: four 8x4-tf32 (8 rows x 16B) submatrices -> 4 regs/thread
__device__ __forceinline__ void ldsm4(uint32_t* r, uint32_t a) {
    asm volatile("ldmatrix.sync.aligned.m8n8.x4.shared.b16 {%0,%1,%2,%3}, [%4];"
                 : "=r"(r[0]), "=r"(r[1]), "=r"(r[2]), "=r"(r[3]) : "r"(a));
}

// m16n8k8 tf32 mma: A row-major (4 regs), B col-major i.e. [n][k] (2 regs)
__device__ __forceinline__ void mma8(float* c, const uint32_t* a, uint32_t b0, uint32_t b1) {
    asm volatile(
        "mma.sync.aligned.m16n8k8.row.col.f32.tf32.tf32.f32 "
        "{%0,%1,%2,%3}, {%4,%5,%6,%7}, {%8,%9}, {%0,%1,%2,%3};"
        : "+f"(c[0]), "+f"(c[1]), "+f"(c[2]), "+f"(c[3])
        : "r"(a[0]), "r"(a[1]), "r"(a[2]), "r"(a[3]), "r"(b0), "r"(b1));
}

// ---------------------------------------------------------------------------
// prep kernels
// ---------------------------------------------------------------------------
__global__ void zround_kernel(const float* __restrict__ z) {
    int i = blockIdx.x * blockDim.x + threadIdx.x;
    float4 v = ((const float4*)z)[i];
    v.x = tf32r(v.x); v.y = tf32r(v.y); v.z = tf32r(v.z); v.w = tf32r(v.w);
    ((float4*)g_zt)[i] = v;
}

__global__ void transpose_kernel(const float* __restrict__ src, float* __restrict__ dst,
                                 int R, int Cc) {
    __shared__ float t[32][33];
    int b  = blockIdx.z;
    int r0 = blockIdx.y * 32, c0 = blockIdx.x * 32;
    const float* s = src + (size_t)b * R * Cc;
    float* d = dst + (size_t)b * R * Cc;
    int tx = threadIdx.x, ty = threadIdx.y;
#pragma unroll
    for (int i = 0; i < 32; i += 8)
        t[ty + i][tx] = tf32r(s[(size_t)(r0 + ty + i) * Cc + c0 + tx]);
    __syncthreads();
#pragma unroll
    for (int i = 0; i < 32; i += 8)
        d[(size_t)(c0 + ty + i) * R + r0 + tx] = t[tx][ty + i];
}

__global__ void q_kernel(const float* __restrict__ z, const float* __restrict__ mu) {
    __shared__ float smu[K_ * NZ_];
    for (int i = threadIdx.x; i < K_ * NZ_; i += blockDim.x) smu[i] = mu[i];
    __syncthreads();
    int gwarp = (blockIdx.x * blockDim.x + threadIdx.x) >> 5;
    int lane  = threadIdx.x & 31;
    if (gwarp >= N_) return;
    const float* zr = z + (size_t)gwarp * NZ_;
    float acc[K_];
#pragma unroll
    for (int k = 0; k < K_; k++) acc[k] = 0.f;
    for (int j = lane; j < NZ_; j += 32) {
        float zj = zr[j];
#pragma unroll
        for (int k = 0; k < K_; k++) {
            float d = zj - smu[k * NZ_ + j];
            acc[k] = fmaf(d, d, acc[k]);
        }
    }
#pragma unroll
    for (int k = 0; k < K_; k++)
#pragma unroll
        for (int o = 16; o > 0; o >>= 1)
            acc[k] += __shfl_xor_sync(0xffffffffu, acc[k], o);
    if (lane == 0) {
        float w[K_], s = 0.f;
#pragma unroll
        for (int k = 0; k < K_; k++) { w[k] = 1.f / (1.f + acc[k]); s += w[k]; }
        float inv = 1.f / s;
#pragma unroll
        for (int k = 0; k < K_; k++) g_q[gwarp * K_ + k] = w[k] * inv;
    }
}

// ---------------------------------------------------------------------------
// fused mma.sync tf32 pipeline, q folded into ReLU, ldmatrix fragment loads.
// ---------------------------------------------------------------------------
#define OFF_BUFA0 0
#define OFF_BUFA1 18432
#define OFF_BUFB0 36864
#define OFF_BUFB1 55296
#define OFF_HS    73728
#define OFF_B2S   141312
#define OFF_B1S   145408
#define SMEM_DYN  (146 * 1024)

__global__ void __launch_bounds__(TPB, 1) fused_mma(
    const float* __restrict__ b1, const float* __restrict__ b2,
    float* __restrict__ out)
{
    extern __shared__ char sm[];
    float* const hs  = (float*)(sm + OFF_HS);
    float* const b2s = (float*)(sm + OFF_B2S);
    float* const b1s = (float*)(sm + OFF_B1S);

    const uint32_t sb = smem_u32(sm);
    const uint32_t uA[2] = { sb + OFF_BUFA0, sb + OFF_BUFA1 };
    const uint32_t uB[2] = { sb + OFF_BUFB0, sb + OFF_BUFB1 };
    const uint32_t uHS   = sb + OFF_HS;

    const int tid  = threadIdx.x;
    const int lane = tid & 31;
    const int warp = tid >> 5;
    const int wm   = warp & 3;       // 0..3 -> row block of 32
    const int wn   = warp >> 2;      // 0..1 -> col block of 64
    const int gr   = lane >> 2;      // group id 0..7
    const int tig  = lane & 3;       // thread in group
    const int rbase = wm * 32;
    const int cbase = wn * 64;
    const int n0   = blockIdx.x * BM;

    // ldmatrix per-lane offsets (bytes)
    const int lr = lane & 7;
    const int lg = lane >> 3;
    const uint32_t aOffT = (uint32_t)(((lr + (lg & 1) * 8) * LDT + (lg >> 1) * 4) * 4);
    const uint32_t aOffH = (uint32_t)(((lr + (lg & 1) * 8) * LDH + (lg >> 1) * 4) * 4);
    const uint32_t bOffT = (uint32_t)(((lr + (lg >> 1) * 8) * LDT + (lg & 1) * 4) * 4);

    for (int i = tid; i < K_ * C_; i += TPB) b2s[i] = b2[i];

    float outacc[64];
#pragma unroll
    for (int i = 0; i < 64; i++) outacc[i] = 0.f;

    for (int k = 0; k < K_; k++) {
        const float* w1base = g_w1t + (size_t)k * H_ * NZ_;
        const float* w2base = g_w2t + (size_t)k * C_ * H_;

        for (int ht = 0; ht < H_; ht += BH) {
            __syncthreads();   // prev chunk fully consumed (hs, b1s, buffers)
            if (tid < BH) b1s[tid] = b1[k * H_ + ht + tid];

            float hacc[64];
#pragma unroll
            for (int i = 0; i < 64; i++) hacc[i] = 0.f;

            // ================= GEMM1: 16 K-subtiles of 32 ==================
            // prologue: stage subtile 0 into buf 0
            {
#pragma unroll
                for (int v = 0; v < 4; v++) {
                    int lin = tid + v * TPB;
                    int row = lin >> 3, seg = lin & 7;
                    cp16(uA[0] + row * (LDT * 4) + seg * 16,
                         g_zt + (size_t)(n0 + row) * NZ_ + seg * 4);
                }
#pragma unroll
                for (int v = 0; v < 4; v++) {
                    int lin = tid + v * TPB;
                    int row = lin >> 3, seg = lin & 7;
                    cp16(uB[0] + row * (LDT * 4) + seg * 16,
                         w1base + (size_t)(ht + row) * NZ_ + seg * 4);
                }
                CP_COMMIT();
            }
            for (int s = 0; s < 16; s++) {
                const int buf = s & 1;
                CP_WAIT0();          // subtile s landed
                __syncthreads();     // all warps past compute(s-1); buf^1 free
                if (s < 15) {        // prefetch subtile s+1 into buf^1
                    const int nb = buf ^ 1;
                    const int zb = (s + 1) * 32;
#pragma unroll
                    for (int v = 0; v < 4; v++) {
                        int lin = tid + v * TPB;
                        int row = lin >> 3, seg = lin & 7;
                        cp16(uA[nb] + row * (LDT * 4) + seg * 16,
                             g_zt + (size_t)(n0 + row) * NZ_ + zb + seg * 4);
                    }
#pragma unroll
                    for (int v = 0; v < 4; v++) {
                        int lin = tid + v * TPB;
                        int row = lin >> 3, seg = lin & 7;
                        cp16(uB[nb] + row * (LDT * 4) + seg * 16,
                             w1base + (size_t)(ht + row) * NZ_ + zb + seg * 4);
                    }
                    CP_COMMIT();
                }
                // compute on buf (ldmatrix fragments)
#pragma unroll
                for (int k8 = 0; k8 < 4; k8++) {
                    uint32_t a0[4], a1[4], bb[4][4];
                    const uint32_t ab = uA[buf] + (uint32_t)(k8 * 32);
                    ldsm4(a0, ab + (uint32_t)(rbase * (LDT * 4)) + aOffT);
                    ldsm4(a1, ab + (uint32_t)((rbase + 16) * (LDT * 4)) + aOffT);
                    const uint32_t bbse = uB[buf] + (uint32_t)(k8 * 32);
#pragma unroll
                    for (int p = 0; p < 4; p++)
                        ldsm4(bb[p], bbse + (uint32_t)((cbase + p * 16) * (LDT * 4)) + bOffT);
#pragma unroll
                    for (int p = 0; p < 4; p++) {
#pragma unroll
                        for (int hf = 0; hf < 2; hf++) {
                            const int tn = p * 2 + hf;
                            mma8(&hacc[tn * 4],       a0, bb[p][hf * 2], bb[p][hf * 2 + 1]);
                            mma8(&hacc[(8 + tn) * 4], a1, bb[p][hf * 2], bb[p][hf * 2 + 1]);
                        }
                    }
                }
            }

            // ---- hs = tf32(q * relu(hacc + b1)) ----
#pragma unroll
            for (int tm = 0; tm < 2; tm++) {
                int r0 = rbase + tm * 16 + gr;
                float qa = g_q[(size_t)(n0 + r0) * K_ + k];
                float qb = g_q[(size_t)(n0 + r0 + 8) * K_ + k];
#pragma unroll
                for (int tn = 0; tn < 8; tn++) {
                    int idx = (tm * 8 + tn) * 4;
                    int c0  = cbase + tn * 8 + 2 * tig;
                    float2 v0, v1;
                    v0.x = tf32r(fmaxf(hacc[idx + 0] + b1s[c0], 0.f) * qa);
                    v0.y = tf32r(fmaxf(hacc[idx + 1] + b1s[c0 + 1], 0.f) * qa);
                    v1.x = tf32r(fmaxf(hacc[idx + 2] + b1s[c0], 0.f) * qb);
                    v1.y = tf32r(fmaxf(hacc[idx + 3] + b1s[c0 + 1], 0.f) * qb);
                    *(float2*)&hs[r0 * LDH + c0] = v0;
                    *(float2*)&hs[(r0 + 8) * LDH + c0] = v1;
                }
            }
            __syncthreads();   // hs visible to all warps

            // ================= GEMM2: 4 K-subtiles of 32 ===================
            {
#pragma unroll
                for (int v = 0; v < 4; v++) {
                    int lin = tid + v * TPB;
                    int row = lin >> 3, seg = lin & 7;   // row = C index
                    cp16(uB[0] + row * (LDT * 4) + seg * 16,
                         w2base + (size_t)row * H_ + ht + seg * 4);
                }
                CP_COMMIT();
            }
            for (int s = 0; s < 4; s++) {
                const int buf = s & 1;
                CP_WAIT0();
                __syncthreads();
                if (s < 3) {
                    const int nb = buf ^ 1;
                    const int hb2 = (s + 1) * 32;
#pragma unroll
                    for (int v = 0; v < 4; v++) {
                        int lin = tid + v * TPB;
                        int row = lin >> 3, seg = lin & 7;
                        cp16(uB[nb] + row * (LDT * 4) + seg * 16,
                             w2base + (size_t)row * H_ + ht + hb2 + seg * 4);
                    }
                    CP_COMMIT();
                }
                const int hb = s * 32;
#pragma unroll
                for (int k8 = 0; k8 < 4; k8++) {
                    uint32_t a0[4], a1[4], bb[4][4];
                    const uint32_t hbse = uHS + (uint32_t)((hb + k8 * 8) * 4);
                    ldsm4(a0, hbse + (uint32_t)(rbase * (LDH * 4)) + aOffH);
                    ldsm4(a1, hbse + (uint32_t)((rbase + 16) * (LDH * 4)) + aOffH);
                    const uint32_t bbse = uB[buf] + (uint32_t)(k8 * 32);
#pragma unroll
                    for (int p = 0; p < 4; p++)
                        ldsm4(bb[p], bbse + (uint32_t)((cbase + p * 16) * (LDT * 4)) + bOffT);
#pragma unroll
                    for (int p = 0; p < 4; p++) {
#pragma unroll
                        for (int hf = 0; hf < 2; hf++) {
                            const int tn = p * 2 + hf;
                            mma8(&outacc[tn * 4],       a0, bb[p][hf * 2], bb[p][hf * 2 + 1]);
                            mma8(&outacc[(8 + tn) * 4], a1, bb[p][hf * 2], bb[p][hf * 2 + 1]);
                        }
                    }
                }
            }
        } // ht
    } // experts

    // ---- epilogue: out = outacc + q @ b2 ----
#pragma unroll
    for (int tm = 0; tm < 2; tm++) {
        int r0 = rbase + tm * 16 + gr;
        float qa[K_], qb[K_];
#pragma unroll
        for (int k = 0; k < K_; k++) {
            qa[k] = g_q[(size_t)(n0 + r0) * K_ + k];
            qb[k] = g_q[(size_t)(n0 + r0 + 8) * K_ + k];
        }
#pragma unroll
        for (int tn = 0; tn < 8; tn++) {
            int idx = (tm * 8 + tn) * 4;
            int c0  = cbase + tn * 8 + 2 * tig;
            float v00 = outacc[idx + 0], v01 = outacc[idx + 1];
            float v10 = outacc[idx + 2], v11 = outacc[idx + 3];
#pragma unroll
            for (int k = 0; k < K_; k++) {
                v00 = fmaf(qa[k], b2s[k * C_ + c0],     v00);
                v01 = fmaf(qa[k], b2s[k * C_ + c0 + 1], v01);
                v10 = fmaf(qb[k], b2s[k * C_ + c0],     v10);
                v11 = fmaf(qb[k], b2s[k * C_ + c0 + 1], v11);
            }
            *(float2*)&out[(size_t)(n0 + r0) * C_ + c0]     = make_float2(v00, v01);
            *(float2*)&out[(size_t)(n0 + r0 + 8) * C_ + c0] = make_float2(v10, v11);
        }
    }
}

// ---------------------------------------------------------------------------
extern "C" void kernel_launch(void* const* d_in, const int* in_sizes, int n_in,
                              void* d_out, int out_size) {
    const float* z  = (const float*)d_in[0];  // [N, NZ]
    const float* mu = (const float*)d_in[1];  // [K, NZ]
    const float* W1 = (const float*)d_in[2];  // [K, NZ, H]
    const float* b1 = (const float*)d_in[3];  // [K, H]
    const float* W2 = (const float*)d_in[4];  // [K, H, C]
    const float* b2 = (const float*)d_in[5];  // [K, C]
    float* out = (float*)d_out;               // [N, C]

    cudaFuncSetAttribute(fused_mma, cudaFuncAttributeMaxDynamicSharedMemorySize, SMEM_DYN);

    zround_kernel<<<(N_ * NZ_ / 4) / TPB, TPB>>>(z);
    float* w1t; cudaGetSymbolAddress((void**)&w1t, g_w1t);
    float* w2t; cudaGetSymbolAddress((void**)&w2t, g_w2t);
    transpose_kernel<<<dim3(H_ / 32, NZ_ / 32, K_), dim3(32, 8)>>>(W1, w1t, NZ_, H_);
    transpose_kernel<<<dim3(C_ / 32, H_ / 32, K_), dim3(32, 8)>>>(W2, w2t, H_, C_);
    q_kernel<<<(N_ * 32) / TPB, TPB>>>(z, mu);
    fused_mma<<<N_ / BM, TPB, SMEM_DYN>>>(b1, b2, out);
}

// round 10
// speedup vs baseline: 4.0302x; 1.0496x over previous
#include <cuda_runtime.h>
#include <cstdint>

#define N_  32768
#define NZ_ 512
#define H_  1024
#define C_  128
#define K_  8
#define TPB 256
#define BM  128          // rows per CTA
#define BH  128          // h columns per chunk
#define LDT 36           // staging tile pitch (floats): 32 + 4 pad
#define LDH 132          // h buffer pitch (floats): 128 + 4 pad

// ---------------- device scratch (static globals: allowed) -----------------
__device__ float g_q[N_ * K_];
__device__ float g_zt[N_ * NZ_];         // tf32-rounded z
__device__ float g_w1t[K_ * H_ * NZ_];   // [K][H][NZ]  (tf32-rounded, n-major)
__device__ float g_w2t[K_ * C_ * H_];    // [K][C][H]   (tf32-rounded, n-major)

// ---------------- helpers ---------------------------------------------------
__device__ __forceinline__ uint32_t smem_u32(const void* p) {
    uint32_t a;
    asm("{ .reg .u64 t; cvta.to.shared.u64 t, %1; cvt.u32.u64 %0, t; }" : "=r"(a) : "l"(p));
    return a;
}
__device__ __forceinline__ float tf32r(float x) {
    uint32_t u; asm("cvt.rna.tf32.f32 %0, %1;" : "=r"(u) : "f"(x));
    return __uint_as_float(u);
}
__device__ __forceinline__ void cp16(uint32_t s, const void* g) {
    asm volatile("cp.async.cg.shared.global [%0], [%1], 16;" :: "r"(s), "l"(g) : "memory");
}
#define CP_COMMIT() asm volatile("cp.async.commit_group;" ::: "memory")
#define CP_WAIT2()  asm volatile("cp.async.wait_group 2;" ::: "memory")

// ldmatrix x4: four 8x4-tf32 (8 rows x 16B) submatrices -> 4 regs/thread
__device__ __forceinline__ void ldsm4(uint32_t* r, uint32_t a) {
    asm volatile("ldmatrix.sync.aligned.m8n8.x4.shared.b16 {%0,%1,%2,%3}, [%4];"
                 : "=r"(r[0]), "=r"(r[1]), "=r"(r[2]), "=r"(r[3]) : "r"(a));
}

// m16n8k8 tf32 mma: A row-major (4 regs), B col-major i.e. [n][k] (2 regs)
__device__ __forceinline__ void mma8(float* c, const uint32_t* a, uint32_t b0, uint32_t b1) {
    asm volatile(
        "mma.sync.aligned.m16n8k8.row.col.f32.tf32.tf32.f32 "
        "{%0,%1,%2,%3}, {%4,%5,%6,%7}, {%8,%9}, {%0,%1,%2,%3};"
        : "+f"(c[0]), "+f"(c[1]), "+f"(c[2]), "+f"(c[3])
        : "r"(a[0]), "r"(a[1]), "r"(a[2]), "r"(a[3]), "r"(b0), "r"(b1));
}

// ---------------------------------------------------------------------------
// prep kernels
// ---------------------------------------------------------------------------
__global__ void zround_kernel(const float* __restrict__ z) {
    int i = blockIdx.x * blockDim.x + threadIdx.x;
    float4 v = ((const float4*)z)[i];
    v.x = tf32r(v.x); v.y = tf32r(v.y); v.z = tf32r(v.z); v.w = tf32r(v.w);
    ((float4*)g_zt)[i] = v;
}

__global__ void transpose_kernel(const float* __restrict__ src, float* __restrict__ dst,
                                 int R, int Cc) {
    __shared__ float t[32][33];
    int b  = blockIdx.z;
    int r0 = blockIdx.y * 32, c0 = blockIdx.x * 32;
    const float* s = src + (size_t)b * R * Cc;
    float* d = dst + (size_t)b * R * Cc;
    int tx = threadIdx.x, ty = threadIdx.y;
#pragma unroll
    for (int i = 0; i < 32; i += 8)
        t[ty + i][tx] = tf32r(s[(size_t)(r0 + ty + i) * Cc + c0 + tx]);
    __syncthreads();
#pragma unroll
    for (int i = 0; i < 32; i += 8)
        d[(size_t)(c0 + ty + i) * R + r0 + tx] = t[tx][ty + i];
}

__global__ void q_kernel(const float* __restrict__ z, const float* __restrict__ mu) {
    __shared__ float smu[K_ * NZ_];
    for (int i = threadIdx.x; i < K_ * NZ_; i += blockDim.x) smu[i] = mu[i];
    __syncthreads();
    int gwarp = (blockIdx.x * blockDim.x + threadIdx.x) >> 5;
    int lane  = threadIdx.x & 31;
    if (gwarp >= N_) return;
    const float* zr = z + (size_t)gwarp * NZ_;
    float acc[K_];
#pragma unroll
    for (int k = 0; k < K_; k++) acc[k] = 0.f;
    for (int j = lane; j < NZ_; j += 32) {
        float zj = zr[j];
#pragma unroll
        for (int k = 0; k < K_; k++) {
            float d = zj - smu[k * NZ_ + j];
            acc[k] = fmaf(d, d, acc[k]);
        }
    }
#pragma unroll
    for (int k = 0; k < K_; k++)
#pragma unroll
        for (int o = 16; o > 0; o >>= 1)
            acc[k] += __shfl_xor_sync(0xffffffffu, acc[k], o);
    if (lane == 0) {
        float w[K_], s = 0.f;
#pragma unroll
        for (int k = 0; k < K_; k++) { w[k] = 1.f / (1.f + acc[k]); s += w[k]; }
        float inv = 1.f / s;
#pragma unroll
        for (int k = 0; k < K_; k++) g_q[gwarp * K_ + k] = w[k] * inv;
    }
}

// ---------------------------------------------------------------------------
// fused mma.sync tf32 pipeline: 4-stage cp.async, q folded into ReLU,
// ldmatrix fragment loads.
// ---------------------------------------------------------------------------
#define STG_BYTES 36864                    // per stage: A 18432 + B 18432
#define OFF_HS    (4 * STG_BYTES)          // 147456
#define OFF_B2S   (OFF_HS + 128 * LDH * 4) // 215040
#define OFF_B1S   (OFF_B2S + 4096)         // 219136
#define SMEM_DYN  (OFF_B1S + 512)          // 219648

// stage subtile ss of GEMM1 (z + W1T) into stage st
#define ISSUE1(ss, st) do {                                                   \
    const int zb_ = (ss) * 32;                                                \
    const uint32_t ua_ = uST[st];                                             \
    const uint32_t ub_ = uST[st] + 18432;                                     \
    _Pragma("unroll")                                                         \
    for (int v = 0; v < 4; v++) {                                             \
        int lin = tid + v * TPB;                                              \
        int row = lin >> 3, seg = lin & 7;                                    \
        cp16(ua_ + row * (LDT * 4) + seg * 16,                                \
             g_zt + (size_t)(n0 + row) * NZ_ + zb_ + seg * 4);                \
    }                                                                         \
    _Pragma("unroll")                                                         \
    for (int v = 0; v < 4; v++) {                                             \
        int lin = tid + v * TPB;                                              \
        int row = lin >> 3, seg = lin & 7;                                    \
        cp16(ub_ + row * (LDT * 4) + seg * 16,                                \
             w1base + (size_t)(ht + row) * NZ_ + zb_ + seg * 4);              \
    }                                                                         \
} while (0)

// stage subtile ss of GEMM2 (W2T only) into stage st's B region
#define ISSUE2(ss, st) do {                                                   \
    const int hb_ = (ss) * 32;                                                \
    const uint32_t ub_ = uST[st] + 18432;                                     \
    _Pragma("unroll")                                                         \
    for (int v = 0; v < 4; v++) {                                             \
        int lin = tid + v * TPB;                                              \
        int row = lin >> 3, seg = lin & 7;                                    \
        cp16(ub_ + row * (LDT * 4) + seg * 16,                                \
             w2base + (size_t)row * H_ + ht + hb_ + seg * 4);                 \
    }                                                                         \
} while (0)

__global__ void __launch_bounds__(TPB, 1) fused_mma(
    const float* __restrict__ b1, const float* __restrict__ b2,
    float* __restrict__ out)
{
    extern __shared__ char sm[];
    float* const hs  = (float*)(sm + OFF_HS);
    float* const b2s = (float*)(sm + OFF_B2S);
    float* const b1s = (float*)(sm + OFF_B1S);

    const uint32_t sb = smem_u32(sm);
    const uint32_t uST[4] = { sb, sb + STG_BYTES, sb + 2 * STG_BYTES, sb + 3 * STG_BYTES };
    const uint32_t uHS = sb + OFF_HS;

    const int tid  = threadIdx.x;
    const int lane = tid & 31;
    const int warp = tid >> 5;
    const int wm   = warp & 3;       // 0..3 -> row block of 32
    const int wn   = warp >> 2;      // 0..1 -> col block of 64
    const int gr   = lane >> 2;      // group id 0..7
    const int tig  = lane & 3;       // thread in group
    const int rbase = wm * 32;
    const int cbase = wn * 64;
    const int n0   = blockIdx.x * BM;

    // ldmatrix per-lane offsets (bytes)
    const int lr = lane & 7;
    const int lg = lane >> 3;
    const uint32_t aOffT = (uint32_t)(((lr + (lg & 1) * 8) * LDT + (lg >> 1) * 4) * 4);
    const uint32_t aOffH = (uint32_t)(((lr + (lg & 1) * 8) * LDH + (lg >> 1) * 4) * 4);
    const uint32_t bOffT = (uint32_t)(((lr + (lg >> 1) * 8) * LDT + (lg & 1) * 4) * 4);

    for (int i = tid; i < K_ * C_; i += TPB) b2s[i] = b2[i];

    float outacc[64];
#pragma unroll
    for (int i = 0; i < 64; i++) outacc[i] = 0.f;

    for (int k = 0; k < K_; k++) {
        const float* w1base = g_w1t + (size_t)k * H_ * NZ_;
        const float* w2base = g_w2t + (size_t)k * C_ * H_;

        for (int ht = 0; ht < H_; ht += BH) {
            __syncthreads();   // prev chunk fully consumed (hs, b1s, all stages)
            if (tid < BH) b1s[tid] = b1[k * H_ + ht + tid];

            float hacc[64];
#pragma unroll
            for (int i = 0; i < 64; i++) hacc[i] = 0.f;

            // ================= GEMM1: 16 K-subtiles, 4-stage pipeline =======
            ISSUE1(0, 0); CP_COMMIT();
            ISSUE1(1, 1); CP_COMMIT();
            ISSUE1(2, 2); CP_COMMIT();
            for (int s = 0; s < 16; s++) {
                const int st = s & 3;
                CP_WAIT2();          // all but 2 newest groups done -> stage s ready
                __syncthreads();     // all warps past compute(s-1): stage (s+3)&3 free
                if (s < 13) { ISSUE1(s + 3, (s + 3) & 3); }
                CP_COMMIT();         // real or empty group (keeps wait accounting exact)
                // compute on stage st
#pragma unroll
                for (int k8 = 0; k8 < 4; k8++) {
                    uint32_t a0[4], a1[4], bb[4][4];
                    const uint32_t ab = uST[st] + (uint32_t)(k8 * 32);
                    ldsm4(a0, ab + (uint32_t)(rbase * (LDT * 4)) + aOffT);
                    ldsm4(a1, ab + (uint32_t)((rbase + 16) * (LDT * 4)) + aOffT);
                    const uint32_t bbse = uST[st] + 18432u + (uint32_t)(k8 * 32);
#pragma unroll
                    for (int p = 0; p < 4; p++)
                        ldsm4(bb[p], bbse + (uint32_t)((cbase + p * 16) * (LDT * 4)) + bOffT);
#pragma unroll
                    for (int p = 0; p < 4; p++) {
#pragma unroll
                        for (int hf = 0; hf < 2; hf++) {
                            const int tn = p * 2 + hf;
                            mma8(&hacc[tn * 4],       a0, bb[p][hf * 2], bb[p][hf * 2 + 1]);
                            mma8(&hacc[(8 + tn) * 4], a1, bb[p][hf * 2], bb[p][hf * 2 + 1]);
                        }
                    }
                }
            }

            // ---- hs = tf32(q * relu(hacc + b1)) ----
#pragma unroll
            for (int tm = 0; tm < 2; tm++) {
                int r0 = rbase + tm * 16 + gr;
                float qa = g_q[(size_t)(n0 + r0) * K_ + k];
                float qb = g_q[(size_t)(n0 + r0 + 8) * K_ + k];
#pragma unroll
                for (int tn = 0; tn < 8; tn++) {
                    int idx = (tm * 8 + tn) * 4;
                    int c0  = cbase + tn * 8 + 2 * tig;
                    float2 v0, v1;
                    v0.x = tf32r(fmaxf(hacc[idx + 0] + b1s[c0], 0.f) * qa);
                    v0.y = tf32r(fmaxf(hacc[idx + 1] + b1s[c0 + 1], 0.f) * qa);
                    v1.x = tf32r(fmaxf(hacc[idx + 2] + b1s[c0], 0.f) * qb);
                    v1.y = tf32r(fmaxf(hacc[idx + 3] + b1s[c0 + 1], 0.f) * qb);
                    *(float2*)&hs[r0 * LDH + c0] = v0;
                    *(float2*)&hs[(r0 + 8) * LDH + c0] = v1;
                }
            }
            __syncthreads();   // hs visible; all warps past GEMM1 (stages free)

            // ================= GEMM2: 4 K-subtiles, pipelined ===============
            ISSUE2(0, 0); CP_COMMIT();
            ISSUE2(1, 1); CP_COMMIT();
            ISSUE2(2, 2); CP_COMMIT();
            for (int s = 0; s < 4; s++) {
                CP_WAIT2();
                __syncthreads();
                if (s < 1) { ISSUE2(3, 3); }
                CP_COMMIT();
                const int hb = s * 32;
#pragma unroll
                for (int k8 = 0; k8 < 4; k8++) {
                    uint32_t a0[4], a1[4], bb[4][4];
                    const uint32_t hbse = uHS + (uint32_t)((hb + k8 * 8) * 4);
                    ldsm4(a0, hbse + (uint32_t)(rbase * (LDH * 4)) + aOffH);
                    ldsm4(a1, hbse + (uint32_t)((rbase + 16) * (LDH * 4)) + aOffH);
                    const uint32_t bbse = uST[s] + 18432u + (uint32_t)(k8 * 32);
#pragma unroll
                    for (int p = 0; p < 4; p++)
                        ldsm4(bb[p], bbse + (uint32_t)((cbase + p * 16) * (LDT * 4)) + bOffT);
#pragma unroll
                    for (int p = 0; p < 4; p++) {
#pragma unroll
                        for (int hf = 0; hf < 2; hf++) {
                            const int tn = p * 2 + hf;
                            mma8(&outacc[tn * 4],       a0, bb[p][hf * 2], bb[p][hf * 2 + 1]);
                            mma8(&outacc[(8 + tn) * 4], a1, bb[p][hf * 2], bb[p][hf * 2 + 1]);
                        }
                    }
                }
            }
        } // ht
    } // experts

    // ---- epilogue: out = outacc + q @ b2 ----
#pragma unroll
    for (int tm = 0; tm < 2; tm++) {
        int r0 = rbase + tm * 16 + gr;
        float qa[K_], qb[K_];
#pragma unroll
        for (int k = 0; k < K_; k++) {
            qa[k] = g_q[(size_t)(n0 + r0) * K_ + k];
            qb[k] = g_q[(size_t)(n0 + r0 + 8) * K_ + k];
        }
#pragma unroll
        for (int tn = 0; tn < 8; tn++) {
            int idx = (tm * 8 + tn) * 4;
            int c0  = cbase + tn * 8 + 2 * tig;
            float v00 = outacc[idx + 0], v01 = outacc[idx + 1];
            float v10 = outacc[idx + 2], v11 = outacc[idx + 3];
#pragma unroll
            for (int k = 0; k < K_; k++) {
                v00 = fmaf(qa[k], b2s[k * C_ + c0],     v00);
                v01 = fmaf(qa[k], b2s[k * C_ + c0 + 1], v01);
                v10 = fmaf(qb[k], b2s[k * C_ + c0],     v10);
                v11 = fmaf(qb[k], b2s[k * C_ + c0 + 1], v11);
            }
            *(float2*)&out[(size_t)(n0 + r0) * C_ + c0]     = make_float2(v00, v01);
            *(float2*)&out[(size_t)(n0 + r0 + 8) * C_ + c0] = make_float2(v10, v11);
        }
    }
}

// ---------------------------------------------------------------------------
extern "C" void kernel_launch(void* const* d_in, const int* in_sizes, int n_in,
                              void* d_out, int out_size) {
    const float* z  = (const float*)d_in[0];  // [N, NZ]
    const float* mu = (const float*)d_in[1];  // [K, NZ]
    const float* W1 = (const float*)d_in[2];  // [K, NZ, H]
    const float* b1 = (const float*)d_in[3];  // [K, H]
    const float* W2 = (const float*)d_in[4];  // [K, H, C]
    const float* b2 = (const float*)d_in[5];  // [K, C]
    float* out = (float*)d_out;               // [N, C]

    cudaFuncSetAttribute(fused_mma, cudaFuncAttributeMaxDynamicSharedMemorySize, SMEM_DYN);

    zround_kernel<<<(N_ * NZ_ / 4) / TPB, TPB>>>(z);
    float* w1t; cudaGetSymbolAddress((void**)&w1t, g_w1t);
    float* w2t; cudaGetSymbolAddress((void**)&w2t, g_w2t);
    transpose_kernel<<<dim3(H_ / 32, NZ_ / 32, K_), dim3(32, 8)>>>(W1, w1t, NZ_, H_);
    transpose_kernel<<<dim3(C_ / 32, H_ / 32, K_), dim3(32, 8)>>>(W2, w2t, H_, C_);
    q_kernel<<<(N_ * 32) / TPB, TPB>>>(z, mu);
    fused_mma<<<N_ / BM, TPB, SMEM_DYN>>>(b1, b2, out);
}